// round 1
// baseline (speedup 1.0000x reference)
#include <cuda_runtime.h>
#include <math.h>

// Problem dims (fixed by setup_inputs): b=4, n=4096, d=128, hid=512, CHUNK=64
#define NTOK 16384
#define D 128
#define HID 512
#define NC 64
#define BATCH 4

// ---------------- scratch (device globals; no allocation allowed) ----------------
__device__ float g_K [NTOK*D];
__device__ float g_V [NTOK*D];
__device__ float g_Q [NTOK*D];
__device__ float g_A [NTOK*HID];   // gelu(z) activations (training pass)
__device__ float g_GP[NTOK*HID];   // gelu'(z)
__device__ float g_dH[NTOK*D];
__device__ float g_dZ[NTOK*HID];
__device__ float g_A2[NTOK*HID];   // gelu(q@w1f) activations (retrieval)
__device__ float g_w2T[D*HID];
__device__ float g_coef[BATCH*NC];
__device__ float g_gfp[128*D];          // per-block partial dgamma (128 M-blocks)
__device__ float g_gf [BATCH*D];
__device__ float g_w1p[64*D*HID];       // (bh*16+s) x (128*512) split-K partials
__device__ float g_w2p[64*D*HID];
__device__ float g_w1f[BATCH*D*HID];
__device__ float g_w2f[BATCH*HID*D];

// ---------------- helpers ----------------
__device__ __forceinline__ float sigm(float x){ return 1.f/(1.f+expf(-x)); }

__device__ __forceinline__ void gelu_both(float x, float& a, float& gp){
    const float c0 = 0.7978845608028654f, c1 = 0.044715f;
    float x2 = x*x;
    float u  = c0*x*(1.f + c1*x2);
    float t  = tanhf(u);
    a  = 0.5f*x*(1.f + t);
    gp = 0.5f*(1.f + t) + 0.5f*x*(1.f - t*t)*c0*(1.f + 3.f*c1*x2);
}
__device__ __forceinline__ float gelu_f(float x){
    const float c0 = 0.7978845608028654f, c1 = 0.044715f;
    float x2 = x*x;
    float t  = tanhf(c0*x*(1.f + c1*x2));
    return 0.5f*x*(1.f + t);
}

// ---------------- GEMM cores: 128x128 tile, BK=16, 256 threads, 8x8/thread ------
// C = A(M,K) @ B(K,N), row-major. As transposed in smem (pad 132).
__device__ __forceinline__ void gemm_nn_core(
    const float* __restrict__ A, int lda,
    const float* __restrict__ B, int ldb,
    int row0, int col0, int K,
    float (&acc)[8][8], float* As, float* Bs)
{
    const int tid = threadIdx.x;
    const int tx = tid & 15, ty = tid >> 4;
    for (int k0 = 0; k0 < K; k0 += 16) {
        #pragma unroll
        for (int t = 0; t < 2; t++) {
            int i4 = tid + t*256;
            int r  = i4 >> 2;
            int kk = (i4 & 3) << 2;
            float4 av = *reinterpret_cast<const float4*>(A + (size_t)(row0 + r)*lda + k0 + kk);
            As[(kk+0)*132 + r] = av.x;
            As[(kk+1)*132 + r] = av.y;
            As[(kk+2)*132 + r] = av.z;
            As[(kk+3)*132 + r] = av.w;
        }
        #pragma unroll
        for (int t = 0; t < 2; t++) {
            int i4 = tid + t*256;
            int kk = i4 >> 5;
            int c  = (i4 & 31) << 2;
            *reinterpret_cast<float4*>(Bs + kk*128 + c) =
                *reinterpret_cast<const float4*>(B + (size_t)(k0+kk)*ldb + col0 + c);
        }
        __syncthreads();
        #pragma unroll
        for (int kk = 0; kk < 16; kk++) {
            float a8[8], b8[8];
            #pragma unroll
            for (int i = 0; i < 8; i++) a8[i] = As[kk*132 + ty*8 + i];
            #pragma unroll
            for (int j = 0; j < 8; j++) b8[j] = Bs[kk*128 + tx*8 + j];
            #pragma unroll
            for (int i = 0; i < 8; i++)
                #pragma unroll
                for (int j = 0; j < 8; j++)
                    acc[i][j] += a8[i]*b8[j];
        }
        __syncthreads();
    }
}

// C[m,n] = sum_t A[t, m0+m] * B[t, n0+n]   (both operands K-major over t)
__device__ __forceinline__ void gemm_tn_core(
    const float* __restrict__ A, int lda, int m0,
    const float* __restrict__ B, int ldb, int n0,
    int t0, int Ks,
    float (&acc)[8][8], float* As, float* Bs)
{
    const int tid = threadIdx.x;
    const int tx = tid & 15, ty = tid >> 4;
    for (int k0 = 0; k0 < Ks; k0 += 16) {
        #pragma unroll
        for (int t = 0; t < 2; t++) {
            int i4 = tid + t*256;
            int kk = i4 >> 5;
            int m  = (i4 & 31) << 2;
            *reinterpret_cast<float4*>(As + kk*128 + m) =
                *reinterpret_cast<const float4*>(A + (size_t)(t0 + k0 + kk)*lda + m0 + m);
            *reinterpret_cast<float4*>(Bs + kk*128 + m) =
                *reinterpret_cast<const float4*>(B + (size_t)(t0 + k0 + kk)*ldb + n0 + m);
        }
        __syncthreads();
        #pragma unroll
        for (int kk = 0; kk < 16; kk++) {
            float a8[8], b8[8];
            #pragma unroll
            for (int i = 0; i < 8; i++) a8[i] = As[kk*128 + ty*8 + i];
            #pragma unroll
            for (int j = 0; j < 8; j++) b8[j] = Bs[kk*128 + tx*8 + j];
            #pragma unroll
            for (int i = 0; i < 8; i++)
                #pragma unroll
                for (int j = 0; j < 8; j++)
                    acc[i][j] += a8[i]*b8[j];
        }
        __syncthreads();
    }
}

// ---------------- kernel 1: per-chunk scalars + scan weights -> coef ------------
__device__ __forceinline__ float bred128(float v){
    __shared__ float wr[4];
    #pragma unroll
    for (int o = 16; o > 0; o >>= 1) v += __shfl_down_sync(0xffffffffu, v, o);
    int tid = threadIdx.x;
    if ((tid & 31) == 0) wr[tid >> 5] = v;
    __syncthreads();
    float r = wr[0] + wr[1] + wr[2] + wr[3];
    __syncthreads();
    return r;
}

__global__ void k_scalars(const float* __restrict__ seq,
                          const float* __restrict__ wlr,  const float* __restrict__ blr,
                          const float* __restrict__ wdec, const float* __restrict__ bdec,
                          const float* __restrict__ wmom, const float* __restrict__ bmom)
{
    int b = blockIdx.x;                 // 4 blocks, 128 threads each
    int tid = threadIdx.x;
    __shared__ float lr[NC], eta[NC], keep[NC];
    for (int c = 0; c < NC; c++) {
        float x = seq[((size_t)b*4096 + c*64)*D + tid];
        float s1 = bred128(x*wlr[tid]);
        float s2 = bred128(x*wdec[tid]);
        float s3 = bred128(x*wmom[tid]);
        if (tid == 0) {
            lr[c]   = sigm(s1 + blr[0]);
            keep[c] = 1.f - sigm(s2 + bdec[0]);
            eta[c]  = sigm(s3 + bmom[0]);
        }
        __syncthreads();
    }
    if (tid == 0) {
        float Aarr[NC];
        Aarr[NC-1] = 1.f;
        float Bv = 1.f;
        for (int j = NC-2; j >= 0; j--) {
            Bv *= keep[j+1];
            Aarr[j] = Bv + eta[j+1]*Aarr[j+1];
        }
        for (int j = 0; j < NC; j++)
            g_coef[b*NC + j] = -Aarr[j]*lr[j]*(2.f/128.f);
    }
}

// ---------------- kernel 2: K/V/Q projections -----------------------------------
__global__ __launch_bounds__(256) void k_proj(const float* __restrict__ seq,
                                              const float* __restrict__ wk,
                                              const float* __restrict__ wv,
                                              const float* __restrict__ wq)
{
    __shared__ float As[16*132], Bs[16*128];
    const float* W = (blockIdx.z == 0) ? wk : (blockIdx.z == 1 ? wv : wq);
    float* O = (blockIdx.z == 0) ? g_K : (blockIdx.z == 1 ? g_V : g_Q);
    int tid = threadIdx.x, tx = tid & 15, ty = tid >> 4;
    int row0 = blockIdx.x * 128;
    float acc[8][8] = {};
    gemm_nn_core(seq, D, W, D, row0, 0, D, acc, As, Bs);
    #pragma unroll
    for (int i = 0; i < 8; i++) {
        int r = row0 + ty*8 + i;
        #pragma unroll
        for (int j = 0; j < 8; j += 4)
            *reinterpret_cast<float4*>(O + (size_t)r*D + tx*8 + j) =
                make_float4(acc[i][j], acc[i][j+1], acc[i][j+2], acc[i][j+3]);
    }
}

// ---------------- kernel 3: Z = K @ w1; A = gelu(Z); GP = gelu'(Z) ---------------
__global__ __launch_bounds__(256) void k_zgelu(const float* __restrict__ w1)
{
    __shared__ float As[16*132], Bs[16*128];
    int tid = threadIdx.x, tx = tid & 15, ty = tid >> 4;
    int row0 = blockIdx.y * 128, col0 = blockIdx.x * 128;
    float acc[8][8] = {};
    gemm_nn_core(g_K, D, w1, HID, row0, col0, D, acc, As, Bs);
    #pragma unroll
    for (int i = 0; i < 8; i++) {
        int r = row0 + ty*8 + i;
        #pragma unroll
        for (int j = 0; j < 8; j++) {
            float a, gp;
            gelu_both(acc[i][j], a, gp);
            int idx = r*HID + col0 + tx*8 + j;
            g_A[idx]  = a;
            g_GP[idx] = gp;
        }
    }
}

// ---------------- kernel 4: transpose w2 ----------------------------------------
__global__ void k_w2t(const float* __restrict__ w2)
{
    int i = blockIdx.x*256 + threadIdx.x;     // 65536 total
    int r = i >> 7, c = i & 127;
    g_w2T[c*HID + r] = w2[i];
}

// ---------------- kernel 5: H = A@w2; rmsnorm bwd; dH; partial dgamma ------------
__global__ __launch_bounds__(256) void k_hback(const float* __restrict__ w2,
                                               const float* __restrict__ gamma)
{
    __shared__ float As[16*132], Bs[16*128];
    __shared__ float red[16*128];
    __shared__ float rowv[128];
    __shared__ float coefrow[128];
    __shared__ float gam[128];
    int tid = threadIdx.x, tx = tid & 15, ty = tid >> 4;
    int row0 = blockIdx.x * 128;              // 128 blocks; never straddles bh
    if (tid < 128) {
        gam[tid] = gamma[tid];
        int tok = row0 + tid;
        coefrow[tid] = g_coef[(tok >> 12)*NC + ((tok & 4095) >> 6)];
    }
    float acc[8][8] = {};
    gemm_nn_core(g_A, HID, w2, D, row0, 0, HID, acc, As, Bs);

    // reduction 1: sum h^2 per row -> inv rms
    #pragma unroll
    for (int i = 0; i < 8; i++) {
        float s = 0;
        #pragma unroll
        for (int j = 0; j < 8; j++) s += acc[i][j]*acc[i][j];
        red[(ty*8+i)*16 + tx] = s;
    }
    __syncthreads();
    if (tid < 128) {
        float s = 0;
        #pragma unroll
        for (int q = 0; q < 16; q++) s += red[tid*16 + q];
        rowv[tid] = 1.f / sqrtf(s*(1.f/128.f) + 1e-6f);
    }
    __syncthreads();
    float ir[8];
    #pragma unroll
    for (int i = 0; i < 8; i++) ir[i] = rowv[ty*8 + i];

    // hn, dpred; reduction 2: dot(dhn, hn) per row
    float dp[8][8];
    #pragma unroll
    for (int i = 0; i < 8; i++) {
        int tok = row0 + ty*8 + i;
        float cf = coefrow[ty*8 + i];
        const float4* K4 = reinterpret_cast<const float4*>(g_K + (size_t)tok*D + tx*8);
        const float4* V4 = reinterpret_cast<const float4*>(g_V + (size_t)tok*D + tx*8);
        float4 ka = K4[0], kb = K4[1], va = V4[0], vb = V4[1];
        float kv[8] = {ka.x,ka.y,ka.z,ka.w,kb.x,kb.y,kb.z,kb.w};
        float vv[8] = {va.x,va.y,va.z,va.w,vb.x,vb.y,vb.z,vb.w};
        float s = 0;
        #pragma unroll
        for (int j = 0; j < 8; j++) {
            int col = tx*8 + j;
            float hn = acc[i][j]*ir[i];
            float e  = hn*gam[col] + kv[j] - vv[j];
            float d_ = cf*e;
            acc[i][j] = hn;
            dp[i][j]  = d_;
            s += d_*gam[col]*hn;
        }
        red[(ty*8+i)*16 + tx] = s;
    }
    __syncthreads();
    if (tid < 128) {
        float s = 0;
        #pragma unroll
        for (int q = 0; q < 16; q++) s += red[tid*16 + q];
        rowv[tid] = s*(1.f/128.f);            // rowdot/128 (ir already in regs)
    }
    __syncthreads();

    // dH = ir*(dhn - hn*rowdot/128)
    #pragma unroll
    for (int i = 0; i < 8; i++) {
        float rd = rowv[ty*8 + i];
        int tok = row0 + ty*8 + i;
        float o[8];
        #pragma unroll
        for (int j = 0; j < 8; j++) {
            int col = tx*8 + j;
            float dhn = dp[i][j]*gam[col];
            o[j] = ir[i]*(dhn - acc[i][j]*rd);
        }
        *reinterpret_cast<float4*>(g_dH + (size_t)tok*D + tx*8)     = make_float4(o[0],o[1],o[2],o[3]);
        *reinterpret_cast<float4*>(g_dH + (size_t)tok*D + tx*8 + 4) = make_float4(o[4],o[5],o[6],o[7]);
    }
    __syncthreads();

    // reduction 3: column sums of dp*hn -> partial dgamma for this block
    #pragma unroll
    for (int j = 0; j < 8; j++) {
        int col = tx*8 + j;
        float s = 0;
        #pragma unroll
        for (int i = 0; i < 8; i++) s += dp[i][j]*acc[i][j];
        red[ty*128 + col] = s;
    }
    __syncthreads();
    if (tid < 128) {
        float s = 0;
        #pragma unroll
        for (int q = 0; q < 16; q++) s += red[q*128 + tid];
        g_gfp[blockIdx.x*128 + tid] = s;      // block -> (bh=bx>>5, slot=bx&31)
    }
}

// ---------------- kernel 6: dZ = (dH @ w2T) * GP --------------------------------
__global__ __launch_bounds__(256) void k_da()
{
    __shared__ float As[16*132], Bs[16*128];
    int tid = threadIdx.x, tx = tid & 15, ty = tid >> 4;
    int row0 = blockIdx.y * 128, col0 = blockIdx.x * 128;
    float acc[8][8] = {};
    gemm_nn_core(g_dH, D, g_w2T, HID, row0, col0, D, acc, As, Bs);
    #pragma unroll
    for (int i = 0; i < 8; i++) {
        int r = row0 + ty*8 + i;
        #pragma unroll
        for (int j = 0; j < 8; j++) {
            int idx = r*HID + col0 + tx*8 + j;
            g_dZ[idx] = acc[i][j]*g_GP[idx];
        }
    }
}

// ---------------- kernels 7/8: split-K grad GEMM partials -----------------------
__global__ __launch_bounds__(256) void k_w1p()
{   // grid (4 ntiles, 1, 64 = bh*16+s); C partial (128x512 per slice)
    __shared__ float As[16*128], Bs[16*128];
    int tid = threadIdx.x, tx = tid & 15, ty = tid >> 4;
    int z = blockIdx.z, bh = z >> 4, s = z & 15;
    int t0 = bh*4096 + s*256;
    int n0 = blockIdx.x * 128;
    float acc[8][8] = {};
    gemm_tn_core(g_K, D, 0, g_dZ, HID, n0, t0, 256, acc, As, Bs);
    float* C = g_w1p + (size_t)z*(D*HID);
    #pragma unroll
    for (int i = 0; i < 8; i++)
        #pragma unroll
        for (int j = 0; j < 8; j += 4)
            *reinterpret_cast<float4*>(C + (ty*8+i)*HID + n0 + tx*8 + j) =
                make_float4(acc[i][j], acc[i][j+1], acc[i][j+2], acc[i][j+3]);
}

__global__ __launch_bounds__(256) void k_w2p()
{   // grid (1, 4 mtiles, 64); C partial (512x128 per slice)
    __shared__ float As[16*128], Bs[16*128];
    int tid = threadIdx.x, tx = tid & 15, ty = tid >> 4;
    int z = blockIdx.z, bh = z >> 4, s = z & 15;
    int t0 = bh*4096 + s*256;
    int m0 = blockIdx.y * 128;
    float acc[8][8] = {};
    gemm_tn_core(g_A, HID, m0, g_dH, D, 0, t0, 256, acc, As, Bs);
    float* C = g_w2p + (size_t)z*(HID*D);
    #pragma unroll
    for (int i = 0; i < 8; i++)
        #pragma unroll
        for (int j = 0; j < 8; j += 4)
            *reinterpret_cast<float4*>(C + (m0 + ty*8+i)*D + tx*8 + j) =
                make_float4(acc[i][j], acc[i][j+1], acc[i][j+2], acc[i][j+3]);
}

// ---------------- kernel 9: deterministic split-K reduce ------------------------
__global__ void k_reduce()
{
    int i = blockIdx.x*256 + threadIdx.x;     // 1024 blocks x 256 = 262144
    if (i < BATCH*D*HID) {
        int bh = i >> 16, off = i & 65535;
        float s1 = 0, s2 = 0;
        #pragma unroll
        for (int s = 0; s < 16; s++) {
            s1 += g_w1p[(size_t)(bh*16 + s)*(D*HID) + off];
            s2 += g_w2p[(size_t)(bh*16 + s)*(HID*D) + off];
        }
        g_w1f[i] = s1;
        g_w2f[i] = s2;
    }
    if (i < BATCH*D) {
        int bh = i >> 7, col = i & 127;
        float s = 0;
        #pragma unroll
        for (int q = 0; q < 32; q++) s += g_gfp[(bh*32 + q)*128 + col];
        g_gf[i] = s;
    }
}

// ---------------- kernel 10: A2 = gelu(Q @ w1f[bh]) -----------------------------
__global__ __launch_bounds__(256) void k_z2()
{   // grid (4 ntiles, 32 mtiles, 4 bh)
    __shared__ float As[16*132], Bs[16*128];
    int tid = threadIdx.x, tx = tid & 15, ty = tid >> 4;
    int bh = blockIdx.z;
    int row0 = bh*4096 + blockIdx.y*128;
    int col0 = blockIdx.x*128;
    float acc[8][8] = {};
    gemm_nn_core(g_Q, D, g_w1f + (size_t)bh*(D*HID), HID, row0, col0, D, acc, As, Bs);
    #pragma unroll
    for (int i = 0; i < 8; i++) {
        int r = row0 + ty*8 + i;
        #pragma unroll
        for (int j = 0; j < 8; j++)
            g_A2[r*HID + col0 + tx*8 + j] = gelu_f(acc[i][j]);
    }
}

// ---------------- kernel 11: out = rmsnorm(A2 @ w2f)*gf + Q ---------------------
__global__ __launch_bounds__(256) void k_out(float* __restrict__ out)
{   // grid (32 mtiles, 1, 4 bh)
    __shared__ float As[16*132], Bs[16*128];
    __shared__ float red[16*128];
    __shared__ float rowv[128];
    int tid = threadIdx.x, tx = tid & 15, ty = tid >> 4;
    int bh = blockIdx.z;
    int row0 = bh*4096 + blockIdx.x*128;
    float acc[8][8] = {};
    gemm_nn_core(g_A2, HID, g_w2f + (size_t)bh*(HID*D), D, row0, 0, HID, acc, As, Bs);
    #pragma unroll
    for (int i = 0; i < 8; i++) {
        float s = 0;
        #pragma unroll
        for (int j = 0; j < 8; j++) s += acc[i][j]*acc[i][j];
        red[(ty*8+i)*16 + tx] = s;
    }
    __syncthreads();
    if (tid < 128) {
        float s = 0;
        #pragma unroll
        for (int q = 0; q < 16; q++) s += red[tid*16 + q];
        rowv[tid] = 1.f / sqrtf(s*(1.f/128.f) + 1e-6f);
    }
    __syncthreads();
    #pragma unroll
    for (int i = 0; i < 8; i++) {
        int tok = row0 + ty*8 + i;
        float irr = rowv[ty*8 + i];
        const float4* Q4 = reinterpret_cast<const float4*>(g_Q + (size_t)tok*D + tx*8);
        float4 qa = Q4[0], qb = Q4[1];
        float qv[8] = {qa.x,qa.y,qa.z,qa.w,qb.x,qb.y,qb.z,qb.w};
        float o[8];
        #pragma unroll
        for (int j = 0; j < 8; j++) {
            int col = tx*8 + j;
            o[j] = acc[i][j]*irr*g_gf[bh*D + col] + qv[j];
        }
        *reinterpret_cast<float4*>(out + (size_t)tok*D + tx*8)     = make_float4(o[0],o[1],o[2],o[3]);
        *reinterpret_cast<float4*>(out + (size_t)tok*D + tx*8 + 4) = make_float4(o[4],o[5],o[6],o[7]);
    }
}

// ---------------- launch --------------------------------------------------------
extern "C" void kernel_launch(void* const* d_in, const int* in_sizes, int n_in,
                              void* d_out, int out_size)
{
    (void)in_sizes; (void)n_in; (void)out_size;
    const float* seq  = (const float*)d_in[0];
    const float* wk   = (const float*)d_in[1];
    const float* wv   = (const float*)d_in[2];
    const float* wq   = (const float*)d_in[3];
    const float* wlr  = (const float*)d_in[4];
    const float* blr  = (const float*)d_in[5];
    const float* wdec = (const float*)d_in[6];
    const float* bdec = (const float*)d_in[7];
    const float* wmom = (const float*)d_in[8];
    const float* bmom = (const float*)d_in[9];
    const float* gamma= (const float*)d_in[10];
    const float* w1   = (const float*)d_in[11];
    const float* w2   = (const float*)d_in[12];
    float* out = (float*)d_out;

    k_scalars<<<BATCH, 128>>>(seq, wlr, blr, wdec, bdec, wmom, bmom);
    k_proj  <<<dim3(NTOK/128, 1, 3), 256>>>(seq, wk, wv, wq);
    k_zgelu <<<dim3(HID/128, NTOK/128), 256>>>(w1);
    k_w2t   <<<(D*HID)/256, 256>>>(w2);
    k_hback <<<NTOK/128, 256>>>(w2, gamma);
    k_da    <<<dim3(HID/128, NTOK/128), 256>>>();
    k_w1p   <<<dim3(HID/128, 1, 64), 256>>>();
    k_w2p   <<<dim3(1, HID/128, 64), 256>>>();
    k_reduce<<<(BATCH*D*HID)/256, 256>>>();
    k_z2    <<<dim3(HID/128, 32, BATCH), 256>>>();
    k_out   <<<dim3(32, 1, BATCH), 256>>>(out);
}

// round 3
// speedup vs baseline: 2.3447x; 2.3447x over previous
#include <cuda_runtime.h>
#include <stdint.h>
#include <math.h>

// dims: b=4, n=4096, d=128, hid=512, CHUNK=64
#define NTOK 16384
#define D 128
#define HID 512
#define NC 64
#define BATCH 4
#define SLICES 8

// ---------------- scratch ----------------
__device__ float g_K [NTOK*D];
__device__ float g_V [NTOK*D];
__device__ float g_Q [NTOK*D];
__device__ float g_A [NTOK*HID];
__device__ float g_GP[NTOK*HID];
__device__ float g_dH[NTOK*D];
__device__ float g_dZ[NTOK*HID];
__device__ float g_A2[NTOK*HID];
__device__ float g_coef[BATCH*NC];
__device__ float g_gfp[128*D];
__device__ float g_gf [BATCH*D];
__device__ float g_w1p[BATCH*SLICES*D*HID];  // per-slice partial of w1f [128][512]
__device__ float g_w2p[BATCH*SLICES*HID*D];  // per-slice partial of w2f [512][128]
__device__ float g_w1f[BATCH*D*HID];
__device__ float g_w2f[BATCH*HID*D];

// ---------------- helpers ----------------
__device__ __forceinline__ float sigm(float x){ return 1.f/(1.f+expf(-x)); }
__device__ __forceinline__ void gelu_both(float x, float& a, float& gp){
    const float c0 = 0.7978845608028654f, c1 = 0.044715f;
    float x2 = x*x;
    float t = tanhf(c0*x*(1.f + c1*x2));
    a  = 0.5f*x*(1.f + t);
    gp = 0.5f*(1.f + t) + 0.5f*x*(1.f - t*t)*c0*(1.f + 3.f*c1*x2);
}
__device__ __forceinline__ float gelu_f(float x){
    const float c0 = 0.7978845608028654f, c1 = 0.044715f;
    float t = tanhf(c0*x*(1.f + c1*x*x));
    return 0.5f*x*(1.f + t);
}
__device__ __forceinline__ uint32_t cvt_tf32(float x){
    uint32_t r; asm("cvt.rna.tf32.f32 %0, %1;" : "=r"(r) : "f"(x)); return r;
}
__device__ __forceinline__ void mma8(float& c0, float& c1, float& c2, float& c3,
                                     uint32_t a0, uint32_t a1, uint32_t a2, uint32_t a3,
                                     uint32_t b0, uint32_t b1){
    asm volatile("mma.sync.aligned.m16n8k8.row.col.f32.tf32.tf32.f32 "
                 "{%0,%1,%2,%3}, {%4,%5,%6,%7}, {%8,%9}, {%0,%1,%2,%3};"
                 : "+f"(c0), "+f"(c1), "+f"(c2), "+f"(c3)
                 : "r"(a0), "r"(a1), "r"(a2), "r"(a3), "r"(b0), "r"(b1));
}

// ------------- warp-mma GEMM core: 128x128 CTA tile, BK=32, 256 thr -------------
// 8 warps = 4 (m) x 2 (n); warp tile 32x64; per-warp 2 mtiles x 8 ntiles m16n8k8.
// AL=0: A stored [m][k] stride 36 (A gmem row-major M x K)
// AL=1: A stored [k][m] stride 136 (A gmem row-major K x M -> transpose for free)
// BL=0: B stored [k][n] stride 136 (B gmem row-major K x N)
// BL=1: B stored [n][k] stride 36  (B gmem row-major N x K -> transpose for free)
#define AS_OFF 0
#define BS_OFF 4608
#define SMP_WORDS 9216          // 36 KB

template<int AL, int BL>
__device__ __forceinline__ void mma_core(const float* __restrict__ Ag, int lda,
                                         const float* __restrict__ Bg, int ldb,
                                         int K, float acc[2][8][4], uint32_t* smp)
{
    const int tid = threadIdx.x;
    const int lane = tid & 31, group = lane >> 2, tg = lane & 3;
    const int wid = tid >> 5, wm = wid & 3, wn = wid >> 2;
    uint32_t* As = smp + AS_OFF;
    uint32_t* Bs = smp + BS_OFF;

    float4 pa[4], pb[4];

    // prefetch chunk 0
    #pragma unroll
    for (int i = 0; i < 4; i++) {
        int idx4 = tid + i*256;
        if (AL == 0) { int r = idx4 >> 3, c4 = idx4 & 7;
            pa[i] = *reinterpret_cast<const float4*>(Ag + (size_t)r*lda + c4*4); }
        else         { int r = idx4 >> 5, c4 = idx4 & 31;
            pa[i] = *reinterpret_cast<const float4*>(Ag + (size_t)r*lda + c4*4); }
        if (BL == 0) { int r = idx4 >> 5, c4 = idx4 & 31;
            pb[i] = *reinterpret_cast<const float4*>(Bg + (size_t)r*ldb + c4*4); }
        else         { int r = idx4 >> 3, c4 = idx4 & 7;
            pb[i] = *reinterpret_cast<const float4*>(Bg + (size_t)r*ldb + c4*4); }
    }

    const int nch = K >> 5;
    for (int c = 0; c < nch; c++) {
        // store prefetched chunk to smem (tf32-converted)
        #pragma unroll
        for (int i = 0; i < 4; i++) {
            int idx4 = tid + i*256;
            uint32_t oa, ob;
            if (AL == 0) { int r = idx4 >> 3, c4 = idx4 & 7;  oa = r*36  + c4*4; }
            else         { int r = idx4 >> 5, c4 = idx4 & 31; oa = r*136 + c4*4; }
            if (BL == 0) { int r = idx4 >> 5, c4 = idx4 & 31; ob = r*136 + c4*4; }
            else         { int r = idx4 >> 3, c4 = idx4 & 7;  ob = r*36  + c4*4; }
            As[oa+0] = cvt_tf32(pa[i].x); As[oa+1] = cvt_tf32(pa[i].y);
            As[oa+2] = cvt_tf32(pa[i].z); As[oa+3] = cvt_tf32(pa[i].w);
            Bs[ob+0] = cvt_tf32(pb[i].x); Bs[ob+1] = cvt_tf32(pb[i].y);
            Bs[ob+2] = cvt_tf32(pb[i].z); Bs[ob+3] = cvt_tf32(pb[i].w);
        }
        __syncthreads();

        // prefetch next chunk
        if (c + 1 < nch) {
            int k0 = (c + 1) * 32;
            #pragma unroll
            for (int i = 0; i < 4; i++) {
                int idx4 = tid + i*256;
                if (AL == 0) { int r = idx4 >> 3, c4 = idx4 & 7;
                    pa[i] = *reinterpret_cast<const float4*>(Ag + (size_t)r*lda + k0 + c4*4); }
                else         { int r = idx4 >> 5, c4 = idx4 & 31;
                    pa[i] = *reinterpret_cast<const float4*>(Ag + (size_t)(k0+r)*lda + c4*4); }
                if (BL == 0) { int r = idx4 >> 5, c4 = idx4 & 31;
                    pb[i] = *reinterpret_cast<const float4*>(Bg + (size_t)(k0+r)*ldb + c4*4); }
                else         { int r = idx4 >> 3, c4 = idx4 & 7;
                    pb[i] = *reinterpret_cast<const float4*>(Bg + (size_t)r*ldb + k0 + c4*4); }
            }
        }

        // compute 4 k-steps of 8
        #pragma unroll
        for (int s = 0; s < 4; s++) {
            const int k = s * 8;
            uint32_t af[2][4];
            #pragma unroll
            for (int mt = 0; mt < 2; mt++) {
                int r = wm*32 + mt*16 + group;
                if (AL == 0) {
                    af[mt][0] = As[(r  )*36 + k + tg];
                    af[mt][1] = As[(r+8)*36 + k + tg];
                    af[mt][2] = As[(r  )*36 + k + tg + 4];
                    af[mt][3] = As[(r+8)*36 + k + tg + 4];
                } else {
                    af[mt][0] = As[(k+tg  )*136 + r];
                    af[mt][1] = As[(k+tg  )*136 + r + 8];
                    af[mt][2] = As[(k+tg+4)*136 + r];
                    af[mt][3] = As[(k+tg+4)*136 + r + 8];
                }
            }
            #pragma unroll
            for (int nt = 0; nt < 8; nt++) {
                int cb = wn*64 + nt*8 + group;
                uint32_t b0, b1;
                if (BL == 0) { b0 = Bs[(k+tg)*136 + cb]; b1 = Bs[(k+tg+4)*136 + cb]; }
                else         { b0 = Bs[cb*36 + k + tg];  b1 = Bs[cb*36 + k + tg + 4]; }
                #pragma unroll
                for (int mt = 0; mt < 2; mt++)
                    mma8(acc[mt][nt][0], acc[mt][nt][1], acc[mt][nt][2], acc[mt][nt][3],
                         af[mt][0], af[mt][1], af[mt][2], af[mt][3], b0, b1);
            }
        }
        __syncthreads();
    }
}

// epilogue index helpers (row/col local to 128x128 tile)
#define ROW_OF(mt, h)  (wm*32 + (mt)*16 + group + 8*(h))
#define COL_OF(nt)     (wn*64 + (nt)*8 + 2*tg)

// ---------------- k_scalars ----------------
__device__ __forceinline__ float bred128(float v){
    __shared__ float wr[4];
    #pragma unroll
    for (int o = 16; o > 0; o >>= 1) v += __shfl_down_sync(0xffffffffu, v, o);
    int tid = threadIdx.x;
    if ((tid & 31) == 0) wr[tid >> 5] = v;
    __syncthreads();
    float r = wr[0] + wr[1] + wr[2] + wr[3];
    __syncthreads();
    return r;
}
__global__ void k_scalars(const float* __restrict__ seq,
                          const float* __restrict__ wlr,  const float* __restrict__ blr,
                          const float* __restrict__ wdec, const float* __restrict__ bdec,
                          const float* __restrict__ wmom, const float* __restrict__ bmom) {
    int b = blockIdx.x;
    int tid = threadIdx.x;
    __shared__ float lr[NC], eta[NC], keep[NC];
    for (int c = 0; c < NC; c++) {
        float x = seq[((size_t)b*4096 + c*64)*D + tid];
        float s1 = bred128(x*wlr[tid]);
        float s2 = bred128(x*wdec[tid]);
        float s3 = bred128(x*wmom[tid]);
        if (tid == 0) {
            lr[c]   = sigm(s1 + blr[0]);
            keep[c] = 1.f - sigm(s2 + bdec[0]);
            eta[c]  = sigm(s3 + bmom[0]);
        }
        __syncthreads();
    }
    if (tid == 0) {
        float Aarr[NC];
        Aarr[NC-1] = 1.f;
        float Bv = 1.f;
        for (int j = NC-2; j >= 0; j--) {
            Bv *= keep[j+1];
            Aarr[j] = Bv + eta[j+1]*Aarr[j+1];
        }
        for (int j = 0; j < NC; j++)
            g_coef[b*NC + j] = -Aarr[j]*lr[j]*(2.f/128.f);
    }
}

// ---------------- G1: K/V/Q = seq @ W ----------------
__global__ __launch_bounds__(256) void g1_proj(const float* __restrict__ seq,
                                               const float* __restrict__ wk,
                                               const float* __restrict__ wv,
                                               const float* __restrict__ wq) {
    __shared__ uint32_t smp[SMP_WORDS];
    const float* W = (blockIdx.z == 0) ? wk : (blockIdx.z == 1 ? wv : wq);
    float* O = (blockIdx.z == 0) ? g_K : (blockIdx.z == 1 ? g_V : g_Q);
    int row0 = blockIdx.x * 128;
    float acc[2][8][4] = {};
    mma_core<0,0>(seq + (size_t)row0*D, D, W, D, D, acc, smp);
    const int tid = threadIdx.x, lane = tid & 31, group = lane >> 2, tg = lane & 3;
    const int wid = tid >> 5, wm = wid & 3, wn = wid >> 2;
    #pragma unroll
    for (int mt = 0; mt < 2; mt++)
        #pragma unroll
        for (int h = 0; h < 2; h++) {
            int tok = row0 + ROW_OF(mt, h);
            #pragma unroll
            for (int nt = 0; nt < 8; nt++)
                *reinterpret_cast<float2*>(O + (size_t)tok*D + COL_OF(nt)) =
                    make_float2(acc[mt][nt][2*h], acc[mt][nt][2*h+1]);
        }
}

// ---------------- G2: Z = K @ w1 -> gelu, gelu' ----------------
__global__ __launch_bounds__(256) void g2_zgelu(const float* __restrict__ w1) {
    __shared__ uint32_t smp[SMP_WORDS];
    int row0 = blockIdx.x*128, n0 = blockIdx.y*128;
    float acc[2][8][4] = {};
    mma_core<0,0>(g_K + (size_t)row0*D, D, w1 + n0, HID, D, acc, smp);
    const int tid = threadIdx.x, lane = tid & 31, group = lane >> 2, tg = lane & 3;
    const int wid = tid >> 5, wm = wid & 3, wn = wid >> 2;
    #pragma unroll
    for (int mt = 0; mt < 2; mt++)
        #pragma unroll
        for (int h = 0; h < 2; h++) {
            int tok = row0 + ROW_OF(mt, h);
            size_t base = (size_t)tok*HID + n0;
            #pragma unroll
            for (int nt = 0; nt < 8; nt++) {
                int cc = COL_OF(nt);
                float a0, p0, a1, p1;
                gelu_both(acc[mt][nt][2*h],   a0, p0);
                gelu_both(acc[mt][nt][2*h+1], a1, p1);
                *reinterpret_cast<float2*>(g_A  + base + cc) = make_float2(a0, a1);
                *reinterpret_cast<float2*>(g_GP + base + cc) = make_float2(p0, p1);
            }
        }
}

// ---------------- G3: H = A @ w2; rmsnorm bwd -> dH, dgamma partial ----------------
__global__ __launch_bounds__(256) void g3_hback(const float* __restrict__ w2,
                                                const float* __restrict__ gamma) {
    __shared__ uint32_t smp[SMP_WORDS];
    __shared__ float gam[128];
    const int tid = threadIdx.x;
    if (tid < 128) gam[tid] = gamma[tid];
    int row0 = blockIdx.x * 128;
    float acc[2][8][4] = {};
    mma_core<0,0>(g_A + (size_t)row0*HID, HID, w2, D, HID, acc, smp);
    const int lane = tid & 31, group = lane >> 2, tg = lane & 3;
    const int wid = tid >> 5, wm = wid & 3, wn = wid >> 2;
    float* rs = reinterpret_cast<float*>(smp);        // [2][128]
    float* cs = reinterpret_cast<float*>(smp) + 256;  // [4][128]

    // row sum of h^2
    #pragma unroll
    for (int mt = 0; mt < 2; mt++)
        #pragma unroll
        for (int h = 0; h < 2; h++) {
            float s = 0;
            #pragma unroll
            for (int nt = 0; nt < 8; nt++)
                s += acc[mt][nt][2*h]*acc[mt][nt][2*h] + acc[mt][nt][2*h+1]*acc[mt][nt][2*h+1];
            s += __shfl_xor_sync(0xffffffffu, s, 1);
            s += __shfl_xor_sync(0xffffffffu, s, 2);
            if (tg == 0) rs[wn*128 + ROW_OF(mt, h)] = s;
        }
    __syncthreads();
    float ir[2][2], cf[2][2];
    #pragma unroll
    for (int mt = 0; mt < 2; mt++)
        #pragma unroll
        for (int h = 0; h < 2; h++) {
            int r = ROW_OF(mt, h);
            ir[mt][h] = rsqrtf((rs[r] + rs[128 + r])*(1.f/128.f) + 1e-6f);
            int tok = row0 + r;
            cf[mt][h] = g_coef[(tok >> 12)*NC + ((tok & 4095) >> 6)];
        }
    __syncthreads();

    // pass 1: rowdot = sum dp*gam*hn
    #pragma unroll
    for (int mt = 0; mt < 2; mt++)
        #pragma unroll
        for (int h = 0; h < 2; h++) {
            int r = ROW_OF(mt, h), tok = row0 + r;
            float irr = ir[mt][h], cfv = cf[mt][h];
            float dsum = 0;
            #pragma unroll
            for (int nt = 0; nt < 8; nt++) {
                int cc = COL_OF(nt);
                float2 kk = *reinterpret_cast<const float2*>(g_K + (size_t)tok*D + cc);
                float2 vv = *reinterpret_cast<const float2*>(g_V + (size_t)tok*D + cc);
                float hn0 = acc[mt][nt][2*h]*irr,   hn1 = acc[mt][nt][2*h+1]*irr;
                float dp0 = cfv*(hn0*gam[cc] + kk.x - vv.x);
                float dp1 = cfv*(hn1*gam[cc+1] + kk.y - vv.y);
                dsum += dp0*gam[cc]*hn0 + dp1*gam[cc+1]*hn1;
            }
            dsum += __shfl_xor_sync(0xffffffffu, dsum, 1);
            dsum += __shfl_xor_sync(0xffffffffu, dsum, 2);
            if (tg == 0) rs[wn*128 + r] = dsum;
        }
    __syncthreads();

    // pass 2: dH + column partials of dp*hn
    float colp[8][2] = {};
    #pragma unroll
    for (int mt = 0; mt < 2; mt++)
        #pragma unroll
        for (int h = 0; h < 2; h++) {
            int r = ROW_OF(mt, h), tok = row0 + r;
            float irr = ir[mt][h], cfv = cf[mt][h];
            float rd = (rs[r] + rs[128 + r])*(1.f/128.f);
            #pragma unroll
            for (int nt = 0; nt < 8; nt++) {
                int cc = COL_OF(nt);
                float2 kk = *reinterpret_cast<const float2*>(g_K + (size_t)tok*D + cc);
                float2 vv = *reinterpret_cast<const float2*>(g_V + (size_t)tok*D + cc);
                float hn0 = acc[mt][nt][2*h]*irr,   hn1 = acc[mt][nt][2*h+1]*irr;
                float dp0 = cfv*(hn0*gam[cc] + kk.x - vv.x);
                float dp1 = cfv*(hn1*gam[cc+1] + kk.y - vv.y);
                float o0 = irr*(dp0*gam[cc]   - hn0*rd);
                float o1 = irr*(dp1*gam[cc+1] - hn1*rd);
                *reinterpret_cast<float2*>(g_dH + (size_t)tok*D + cc) = make_float2(o0, o1);
                colp[nt][0] += dp0*hn0;
                colp[nt][1] += dp1*hn1;
            }
        }
    #pragma unroll
    for (int nt = 0; nt < 8; nt++)
        #pragma unroll
        for (int j = 0; j < 2; j++) {
            float v = colp[nt][j];
            v += __shfl_xor_sync(0xffffffffu, v, 4);
            v += __shfl_xor_sync(0xffffffffu, v, 8);
            v += __shfl_xor_sync(0xffffffffu, v, 16);
            if (group == 0) cs[wm*128 + COL_OF(nt) + j] = v;
        }
    __syncthreads();
    if (tid < 128) {
        float s = cs[tid] + cs[128 + tid] + cs[256 + tid] + cs[384 + tid];
        g_gfp[blockIdx.x*128 + tid] = s;
    }
}

// ---------------- G4: dZ = (dH @ w2^T) * GP ----------------
__global__ __launch_bounds__(256) void g4_da(const float* __restrict__ w2) {
    __shared__ uint32_t smp[SMP_WORDS];
    int row0 = blockIdx.x*128, n0 = blockIdx.y*128;
    float acc[2][8][4] = {};
    mma_core<0,1>(g_dH + (size_t)row0*D, D, w2 + (size_t)n0*D, D, D, acc, smp);
    const int tid = threadIdx.x, lane = tid & 31, group = lane >> 2, tg = lane & 3;
    const int wid = tid >> 5, wm = wid & 3, wn = wid >> 2;
    #pragma unroll
    for (int mt = 0; mt < 2; mt++)
        #pragma unroll
        for (int h = 0; h < 2; h++) {
            int tok = row0 + ROW_OF(mt, h);
            size_t base = (size_t)tok*HID + n0;
            #pragma unroll
            for (int nt = 0; nt < 8; nt++) {
                int cc = COL_OF(nt);
                float2 gp = *reinterpret_cast<const float2*>(g_GP + base + cc);
                *reinterpret_cast<float2*>(g_dZ + base + cc) =
                    make_float2(acc[mt][nt][2*h]*gp.x, acc[mt][nt][2*h+1]*gp.y);
            }
        }
}

// ---------------- G5a: w1f partial[z] = K_slice^T @ dZ_slice ----------------
__global__ __launch_bounds__(256) void g5_w1p() {
    __shared__ uint32_t smp[SMP_WORDS];
    int n0 = blockIdx.x * 128;
    int z = blockIdx.z, bh = z >> 3, sl = z & 7;
    int t0 = bh*4096 + sl*512;
    float acc[2][8][4] = {};
    mma_core<1,0>(g_K + (size_t)t0*D, D, g_dZ + (size_t)t0*HID + n0, HID, 512, acc, smp);
    const int tid = threadIdx.x, lane = tid & 31, group = lane >> 2, tg = lane & 3;
    const int wid = tid >> 5, wm = wid & 3, wn = wid >> 2;
    float* C = g_w1p + (size_t)z*(D*HID);
    #pragma unroll
    for (int mt = 0; mt < 2; mt++)
        #pragma unroll
        for (int h = 0; h < 2; h++) {
            int r = ROW_OF(mt, h);
            #pragma unroll
            for (int nt = 0; nt < 8; nt++)
                *reinterpret_cast<float2*>(C + (size_t)r*HID + n0 + COL_OF(nt)) =
                    make_float2(acc[mt][nt][2*h], acc[mt][nt][2*h+1]);
        }
}

// ---------------- G5b: w2f partial[z] = A_slice^T @ dH_slice ----------------
__global__ __launch_bounds__(256) void g5_w2p() {
    __shared__ uint32_t smp[SMP_WORDS];
    int m0 = blockIdx.x * 128;
    int z = blockIdx.z, bh = z >> 3, sl = z & 7;
    int t0 = bh*4096 + sl*512;
    float acc[2][8][4] = {};
    mma_core<1,0>(g_A + (size_t)t0*HID + m0, HID, g_dH + (size_t)t0*D, D, 512, acc, smp);
    const int tid = threadIdx.x, lane = tid & 31, group = lane >> 2, tg = lane & 3;
    const int wid = tid >> 5, wm = wid & 3, wn = wid >> 2;
    float* C = g_w2p + (size_t)z*(HID*D);
    #pragma unroll
    for (int mt = 0; mt < 2; mt++)
        #pragma unroll
        for (int h = 0; h < 2; h++) {
            int r = m0 + ROW_OF(mt, h);
            #pragma unroll
            for (int nt = 0; nt < 8; nt++)
                *reinterpret_cast<float2*>(C + (size_t)r*D + COL_OF(nt)) =
                    make_float2(acc[mt][nt][2*h], acc[mt][nt][2*h+1]);
        }
}

// ---------------- reduce split-K partials + dgamma ----------------
__global__ void k_reduce() {
    int i = blockIdx.x*256 + threadIdx.x;   // 262144
    if (i < BATCH*D*HID) {
        int bh = i >> 16, off = i & 65535;
        float s1 = 0, s2 = 0;
        #pragma unroll
        for (int s = 0; s < SLICES; s++) {
            s1 += g_w1p[(size_t)(bh*SLICES + s)*(D*HID) + off];
            s2 += g_w2p[(size_t)(bh*SLICES + s)*(HID*D) + off];
        }
        g_w1f[i] = s1;
        g_w2f[i] = s2;
    }
    if (i < BATCH*D) {
        int bh = i >> 7, col = i & 127;
        float s = 0;
        #pragma unroll
        for (int q = 0; q < 32; q++) s += g_gfp[(bh*32 + q)*128 + col];
        g_gf[i] = s;
    }
}

// ---------------- G6: A2 = gelu(Q @ w1f) ----------------
__global__ __launch_bounds__(256) void g6_z2() {
    __shared__ uint32_t smp[SMP_WORDS];
    int row0 = blockIdx.x*128, n0 = blockIdx.y*128;
    int bh = row0 >> 12;
    float acc[2][8][4] = {};
    mma_core<0,0>(g_Q + (size_t)row0*D, D, g_w1f + (size_t)bh*(D*HID) + n0, HID, D, acc, smp);
    const int tid = threadIdx.x, lane = tid & 31, group = lane >> 2, tg = lane & 3;
    const int wid = tid >> 5, wm = wid & 3, wn = wid >> 2;
    #pragma unroll
    for (int mt = 0; mt < 2; mt++)
        #pragma unroll
        for (int h = 0; h < 2; h++) {
            int tok = row0 + ROW_OF(mt, h);
            size_t base = (size_t)tok*HID + n0;
            #pragma unroll
            for (int nt = 0; nt < 8; nt++) {
                int cc = COL_OF(nt);
                *reinterpret_cast<float2*>(g_A2 + base + cc) =
                    make_float2(gelu_f(acc[mt][nt][2*h]), gelu_f(acc[mt][nt][2*h+1]));
            }
        }
}

// ---------------- G7: out = rmsnorm(A2 @ w2f)*gf + Q ----------------
__global__ __launch_bounds__(256) void g7_out(float* __restrict__ out) {
    __shared__ uint32_t smp[SMP_WORDS];
    __shared__ float gfs[128];
    const int tid = threadIdx.x;
    int row0 = blockIdx.x * 128;
    int bh = row0 >> 12;
    if (tid < 128) gfs[tid] = g_gf[bh*D + tid];
    float acc[2][8][4] = {};
    mma_core<0,0>(g_A2 + (size_t)row0*HID, HID, g_w2f + (size_t)bh*(HID*D), D, HID, acc, smp);
    const int lane = tid & 31, group = lane >> 2, tg = lane & 3;
    const int wid = tid >> 5, wm = wid & 3, wn = wid >> 2;
    float* rs = reinterpret_cast<float*>(smp);  // [2][128]
    #pragma unroll
    for (int mt = 0; mt < 2; mt++)
        #pragma unroll
        for (int h = 0; h < 2; h++) {
            float s = 0;
            #pragma unroll
            for (int nt = 0; nt < 8; nt++)
                s += acc[mt][nt][2*h]*acc[mt][nt][2*h] + acc[mt][nt][2*h+1]*acc[mt][nt][2*h+1];
            s += __shfl_xor_sync(0xffffffffu, s, 1);
            s += __shfl_xor_sync(0xffffffffu, s, 2);
            if (tg == 0) rs[wn*128 + ROW_OF(mt, h)] = s;
        }
    __syncthreads();
    #pragma unroll
    for (int mt = 0; mt < 2; mt++)
        #pragma unroll
        for (int h = 0; h < 2; h++) {
            int r = ROW_OF(mt, h), tok = row0 + r;
            float irr = rsqrtf((rs[r] + rs[128 + r])*(1.f/128.f) + 1e-6f);
            #pragma unroll
            for (int nt = 0; nt < 8; nt++) {
                int cc = COL_OF(nt);
                float2 qq = *reinterpret_cast<const float2*>(g_Q + (size_t)tok*D + cc);
                *reinterpret_cast<float2*>(out + (size_t)tok*D + cc) =
                    make_float2(acc[mt][nt][2*h]*irr*gfs[cc] + qq.x,
                                acc[mt][nt][2*h+1]*irr*gfs[cc+1] + qq.y);
            }
        }
}

// ---------------- launch ----------------
extern "C" void kernel_launch(void* const* d_in, const int* in_sizes, int n_in,
                              void* d_out, int out_size) {
    (void)in_sizes; (void)n_in; (void)out_size;
    const float* seq  = (const float*)d_in[0];
    const float* wk   = (const float*)d_in[1];
    const float* wv   = (const float*)d_in[2];
    const float* wq   = (const float*)d_in[3];
    const float* wlr  = (const float*)d_in[4];
    const float* blr  = (const float*)d_in[5];
    const float* wdec = (const float*)d_in[6];
    const float* bdec = (const float*)d_in[7];
    const float* wmom = (const float*)d_in[8];
    const float* bmom = (const float*)d_in[9];
    const float* gamma= (const float*)d_in[10];
    const float* w1   = (const float*)d_in[11];
    const float* w2   = (const float*)d_in[12];
    float* out = (float*)d_out;

    k_scalars<<<BATCH, 128>>>(seq, wlr, blr, wdec, bdec, wmom, bmom);
    g1_proj <<<dim3(NTOK/128, 1, 3), 256>>>(seq, wk, wv, wq);
    g2_zgelu<<<dim3(NTOK/128, HID/128), 256>>>(w1);
    g3_hback<<<NTOK/128, 256>>>(w2, gamma);
    g4_da   <<<dim3(NTOK/128, HID/128), 256>>>(w2);
    g5_w1p  <<<dim3(HID/128, 1, BATCH*SLICES), 256>>>();
    g5_w2p  <<<dim3(HID/128, 1, BATCH*SLICES), 256>>>();
    k_reduce<<<(BATCH*D*HID)/256, 256>>>();
    g6_z2   <<<dim3(NTOK/128, HID/128), 256>>>();
    g7_out  <<<NTOK/128, 256>>>(out);
}